// round 9
// baseline (speedup 1.0000x reference)
#include <cuda_runtime.h>
#include <math.h>

#define Tn 1024
#define Bn 128
#define Nn 256
#define Dn 256

// ---------------- static device scratch ----------------
// g_XP[((t*4 + g)*768 + col)*128 + b]
__device__ float g_XP[(size_t)Bn * Tn * 3072];
// double-buffered state: [parity][gi][k][b32], gi = g*4 + pgroup
__device__ float g_Hd [2 * 16 * 8192];
__device__ float g_RHd[2 * 16 * 8192];
__device__ unsigned g_seq[128];     // [gi*8 + cs] monotonic publish counters
__device__ unsigned g_headbar;

// ---------------- f32x2 helpers ----------------
static __device__ __forceinline__ unsigned long long pk2(float lo, float hi) {
    unsigned long long r;
    asm("mov.b64 %0, {%1, %2};" : "=l"(r) : "f"(lo), "f"(hi));
    return r;
}
static __device__ __forceinline__ void up2(unsigned long long v, float& lo, float& hi) {
    asm("mov.b64 {%0, %1}, %2;" : "=f"(lo), "=f"(hi) : "l"(v));
}
static __device__ __forceinline__ void fma2(unsigned long long& d,
                                            unsigned long long a,
                                            unsigned long long b) {
    asm("fma.rn.f32x2 %0, %1, %2, %0;" : "+l"(d) : "l"(a), "l"(b));
}
static __device__ __forceinline__ float sigf(float x) {
    return 1.0f / (1.0f + __expf(-x));
}
static __device__ __forceinline__ float tanhfast(float x) {
    float e = __expf(2.0f * x);
    return 1.0f - 2.0f / (e + 1.0f);
}

// ---------------- cp.async helpers ----------------
static __device__ __forceinline__ void cpa16(void* smem, const void* gmem) {
    unsigned s = (unsigned)__cvta_generic_to_shared(smem);
    asm volatile("cp.async.cg.shared.global [%0], [%1], 16;" :: "r"(s), "l"(gmem));
}
#define CPA_COMMIT() asm volatile("cp.async.commit_group;")
#define CPA_WAIT(n)  asm volatile("cp.async.wait_group %0;" :: "n"(n))

// wait until 4 consecutive flags are all >= v (one LDG.128 per poll)
static __device__ __forceinline__ void wait4(const unsigned* f, unsigned v) {
    unsigned a, b, c, d;
    while (true) {
        asm volatile("ld.global.cg.v4.u32 {%0,%1,%2,%3}, [%4];"
                     : "=r"(a), "=r"(b), "=r"(c), "=r"(d) : "l"(f));
        if (a >= v && b >= v && c >= v && d >= v) break;
        __nanosleep(20);
    }
}

// ---------------- init ----------------
__global__ void init_kernel(const float* __restrict__ ic_h0,
                            const float* __restrict__ ci_h0,
                            float* __restrict__ out) {
    int i = blockIdx.x * 256 + threadIdx.x;
    if (i < 16 * 8192) {            // H parity slot 0
        int gi = i >> 13;
        int g  = gi >> 2;
        int k  = (i >> 5) & 255;
        const float* h0 = (g < 2) ? ic_h0 : ci_h0;
        g_Hd[i] = h0[(g & 1) * Dn + k];
    }
    if (i < Bn * Dn) {
        int b = i / Dn, d = i % Dn;
        float* ci = out + 32768;
        ci[((size_t)b * Tn) * 512 + d] = 0.0f;
        ci[((size_t)b * Tn + (Tn - 1)) * 512 + 256 + d] = 0.0f;
    }
    if (i < 128) g_seq[i] = 0u;
    if (i == 200) g_headbar = 0u;
}

// ---------------- xproj SGEMM (f32x2, transposed output) ----------------
__global__ void __launch_bounds__(256) xproj_kernel(
    const float* __restrict__ X,
    const float* __restrict__ W0, const float* __restrict__ W1,
    const float* __restrict__ W2, const float* __restrict__ W3,
    const float* __restrict__ b0, const float* __restrict__ b1,
    const float* __restrict__ b2, const float* __restrict__ b3)
{
    __shared__ float As[8][128];
    __shared__ float Bs[8][128];

    const int t_  = blockIdx.y;
    const int n0  = blockIdx.x * 128;
    const int g   = n0 / 768;
    const int nc  = n0 - g * 768;
    const float* W    = (g == 0) ? W0 : (g == 1) ? W1 : (g == 2) ? W2 : W3;
    const float* bias = (g == 0) ? b0 : (g == 1) ? b1 : (g == 2) ? b2 : b3;

    const int tid  = threadIdx.x;
    const int warp = tid >> 5, lane = tid & 31;
    const int row0 = (warp & 3) * 32 + (lane >> 3) * 8;
    const int col0 = (warp >> 2) * 64 + (lane & 7) * 8;

    const int am = tid >> 1, ak = (tid & 1) * 4;
    const int bk = tid >> 5, bn = (tid & 31) * 4;

    unsigned long long acc[8][4];
    #pragma unroll
    for (int i = 0; i < 8; i++)
        #pragma unroll
        for (int j = 0; j < 4; j++) acc[i][j] = 0ULL;

    for (int k0 = 0; k0 < 256; k0 += 8) {
        float4 av = __ldg((const float4*)&X[(size_t)am * (Tn * 256) + t_ * 256 + k0 + ak]);
        float4 bv = __ldg((const float4*)&W[(size_t)(k0 + bk) * 768 + nc + bn]);
        __syncthreads();
        As[ak + 0][am] = av.x; As[ak + 1][am] = av.y;
        As[ak + 2][am] = av.z; As[ak + 3][am] = av.w;
        *(float4*)&Bs[bk][bn] = bv;
        __syncthreads();

        #pragma unroll
        for (int kk = 0; kk < 8; ++kk) {
            float4 a0 = *(const float4*)&As[kk][row0];
            float4 a1 = *(const float4*)&As[kk][row0 + 4];
            ulonglong2 b01 = *(const ulonglong2*)&Bs[kk][col0];
            ulonglong2 b23 = *(const ulonglong2*)&Bs[kk][col0 + 4];
            float ar[8] = {a0.x, a0.y, a0.z, a0.w, a1.x, a1.y, a1.z, a1.w};
            #pragma unroll
            for (int i = 0; i < 8; i++) {
                unsigned long long ai = pk2(ar[i], ar[i]);
                fma2(acc[i][0], ai, b01.x);
                fma2(acc[i][1], ai, b01.y);
                fma2(acc[i][2], ai, b23.x);
                fma2(acc[i][3], ai, b23.y);
            }
        }
    }

    float c[8][8];
    #pragma unroll
    for (int i = 0; i < 8; i++) {
        up2(acc[i][0], c[i][0], c[i][1]);
        up2(acc[i][1], c[i][2], c[i][3]);
        up2(acc[i][2], c[i][4], c[i][5]);
        up2(acc[i][3], c[i][6], c[i][7]);
    }
    #pragma unroll
    for (int j = 0; j < 8; j++) {
        float bb = bias[nc + col0 + j];
        size_t base = ((size_t)(t_ * 4 + g) * 768 + nc + col0 + j) * 128 + row0;
        float4 v0 = make_float4(c[0][j] + bb, c[1][j] + bb, c[2][j] + bb, c[3][j] + bb);
        float4 v1 = make_float4(c[4][j] + bb, c[5][j] + bb, c[6][j] + bb, c[7][j] + bb);
        __stcg((float4*)&g_XP[base],     v0);
        __stcg((float4*)&g_XP[base + 4], v1);
    }
}

// ---------------- scan smem layout (floats) ----------------
#define HS_OFF   0                        // 8192  : H/RH batch-slice [256][32]
#define U1_OFF   8192                     // 16384 : zr U slab [256][64]
#define U2_OFF   (U1_OFF + 16384)         // 8192  : hh U slab [256][32]
#define XP_OFF   (U2_OFF + 8192)          // 6144  : XP double buffer [2][96][32]
#define ZS_OFF   (XP_OFF + 6144)          // 1024  : z gate [32][32]
#define HSV_OFF  (ZS_OFF + 1024)          // 1024  : saved old-H [32][32]
#define SCAN_SMEM_FLOATS (HSV_OFF + 1024)
#define SCAN_SMEM_BYTES  (SCAN_SMEM_FLOATS * 4)   // 163840 B

// ---------------- persistent scan: 128 CTAs = 4 GRU x 4 bgroup x 8 colslice ----------------
__global__ void __launch_bounds__(256, 1) scan_kernel(
    const float* __restrict__ U0, const float* __restrict__ U1,
    const float* __restrict__ U2, const float* __restrict__ U3,
    const float* __restrict__ Wm, const float* __restrict__ bm,
    const float* __restrict__ Wlv, const float* __restrict__ blv,
    float* __restrict__ out)
{
    extern __shared__ float sm[];
    float* Hs   = sm + HS_OFF;
    float* U1s  = sm + U1_OFF;
    float* U2s  = sm + U2_OFF;
    float* XPd  = sm + XP_OFF;
    float* Zs   = sm + ZS_OFF;
    float* HsSv = sm + HSV_OFF;

    const int g   = blockIdx.x >> 5;
    const int pg  = (blockIdx.x >> 3) & 3;
    const int cs  = blockIdx.x & 7;
    const int d0  = cs * 32;
    const int gi  = g * 4 + pg;
    const int tid = threadIdx.x;
    const int b   = tid & 31;
    const int jo  = tid >> 5;
    const float* U = (g == 0) ? U0 : (g == 1) ? U1 : (g == 2) ? U2 : U3;
    const unsigned* flags = g_seq + gi * 8;

    // resident U slabs
    for (int i = tid; i < 256 * 64; i += 256) {
        int k = i >> 6, jj = i & 63;
        int col = (jj < 32) ? (d0 + jj) : (256 + d0 + jj - 32);
        U1s[i] = U[k * 768 + col];
    }
    for (int i = tid; i < 256 * 32; i += 256) {
        int k = i >> 5, jj = i & 31;
        U2s[i] = U[k * 768 + 512 + d0 + jj];
    }

    float* ci = out + 32768;
    const int j1 = jo * 8;
    const int j2 = jo * 4;

    // ---- prologue: stage XP(0) only ----
    {
        int t0 = (g & 1) ? (Tn - 1) : 0;
        const float* xpb = g_XP + ((size_t)t0 * 4 + g) * 98304;
        #pragma unroll
        for (int i = 0; i < 3; i++) {
            int idx = i * 256 + tid;
            int cl = idx >> 3, seg = idx & 7;
            int gcol = (cl < 32) ? (d0 + cl) : (cl < 64) ? (256 + d0 + cl - 32)
                                             : (512 + d0 + cl - 64);
            cpa16(XPd + cl * 32 + seg * 4, xpb + gcol * 128 + pg * 32 + seg * 4);
        }
        CPA_COMMIT();
        CPA_WAIT(0);
    }
    __syncthreads();

    for (int s = 0; s < Tn; s++) {
        const float* XPc = XPd + (s & 1) * 3072;
        const unsigned sv = (unsigned)(2 * s);

        // ---- prefetch XP(s+1) ----
        {
            int sn = (s < Tn - 1) ? (s + 1) : s;
            int tn_ = (g & 1) ? (Tn - 1 - sn) : sn;
            const float* xpb = g_XP + ((size_t)tn_ * 4 + g) * 98304;
            float* dst = XPd + ((s + 1) & 1) * 3072;
            #pragma unroll
            for (int i = 0; i < 3; i++) {
                int idx = i * 256 + tid;
                int cl = idx >> 3, seg = idx & 7;
                int gcol = (cl < 32) ? (d0 + cl) : (cl < 64) ? (256 + d0 + cl - 32)
                                                 : (512 + d0 + cl - 64);
                cpa16(dst + cl * 32 + seg * 4, xpb + gcol * 128 + pg * 32 + seg * 4);
            }
            CPA_COMMIT();
        }

        // ---- stage H (read slot s&1) with per-chunk flag waits ----
        const float* Hrd = g_Hd + (((s & 1) << 4) + gi) * 8192;
        wait4(flags, sv);                 // producers 0..3 published H for step s
        #pragma unroll
        for (int r = 0; r < 4; r++)
            cpa16(Hs + (r * 256 + tid) * 4, Hrd + (r * 256 + tid) * 4);
        CPA_COMMIT();
        wait4(flags + 4, sv);             // producers 4..7
        #pragma unroll
        for (int r = 0; r < 4; r++)
            cpa16(Hs + 4096 + (r * 256 + tid) * 4, Hrd + 4096 + (r * 256 + tid) * 4);
        CPA_COMMIT();

        // ---- phase 1: zr pre-activation ----
        unsigned long long acc[4];
        #pragma unroll
        for (int p = 0; p < 4; p++)
            acc[p] = pk2(XPc[(j1 + 2 * p) * 32 + b], XPc[(j1 + 2 * p + 1) * 32 + b]);

        CPA_WAIT(1);      // retires XP prefetch + H chunk1
        __syncthreads();
        {
            const float* u1p = U1s + j1;
            const float* hp  = Hs + b;
            #pragma unroll 8
            for (int k = 0; k < 128; k++) {
                ulonglong2 ua = *(const ulonglong2*)(u1p);
                ulonglong2 ub = *(const ulonglong2*)(u1p + 4);
                float h = *hp;
                unsigned long long hd = pk2(h, h);
                fma2(acc[0], ua.x, hd); fma2(acc[1], ua.y, hd);
                fma2(acc[2], ub.x, hd); fma2(acc[3], ub.y, hd);
                u1p += 64; hp += 32;
            }
        }
        CPA_WAIT(0);
        __syncthreads();
        {
            const float* u1p = U1s + 128 * 64 + j1;
            const float* hp  = Hs + 128 * 32 + b;
            #pragma unroll 8
            for (int k = 0; k < 128; k++) {
                ulonglong2 ua = *(const ulonglong2*)(u1p);
                ulonglong2 ub = *(const ulonglong2*)(u1p + 4);
                float h = *hp;
                unsigned long long hd = pk2(h, h);
                fma2(acc[0], ua.x, hd); fma2(acc[1], ua.y, hd);
                fma2(acc[2], ub.x, hd); fma2(acc[3], ub.y, hd);
                u1p += 64; hp += 32;
            }
        }

        // epilogue: z -> Zs, r -> r*h -> g_RHd[slot s&1], save old-H
        float* RHw = g_RHd + (((s & 1) << 4) + gi) * 8192;
        {
            float v[8];
            #pragma unroll
            for (int p = 0; p < 4; p++) up2(acc[p], v[2 * p], v[2 * p + 1]);
            if (jo < 4) {
                #pragma unroll
                for (int j = 0; j < 8; j++)
                    Zs[(j1 + j) * 32 + b] = sigf(v[j]);
            } else {
                int jb = j1 - 32;
                #pragma unroll
                for (int j = 0; j < 8; j++) {
                    int d = d0 + jb + j;
                    float rh = sigf(v[j]) * Hs[d * 32 + b];
                    __stcg(RHw + d * 32 + b, rh);
                }
            }
            float4 hv = *(const float4*)(Hs + d0 * 32 + tid * 4);
            *(float4*)(HsSv + tid * 4) = hv;
        }
        __syncthreads();
        if (tid == 0) {
            __threadfence();
            *((volatile unsigned*)&g_seq[gi * 8 + cs]) = sv + 1u;
        }

        // ---- stage RH (read slot s&1) with per-chunk flag waits ----
        const float* RHrd = RHw;
        wait4(flags, sv + 1u);
        #pragma unroll
        for (int r = 0; r < 4; r++)
            cpa16(Hs + (r * 256 + tid) * 4, RHrd + (r * 256 + tid) * 4);
        CPA_COMMIT();
        wait4(flags + 4, sv + 1u);
        #pragma unroll
        for (int r = 0; r < 4; r++)
            cpa16(Hs + 4096 + (r * 256 + tid) * 4, RHrd + 4096 + (r * 256 + tid) * 4);
        CPA_COMMIT();

        // ---- phase 2: candidate + update ----
        unsigned long long acc2[2];
        #pragma unroll
        for (int p = 0; p < 2; p++)
            acc2[p] = pk2(XPc[(64 + j2 + 2 * p) * 32 + b],
                          XPc[(64 + j2 + 2 * p + 1) * 32 + b]);

        CPA_WAIT(1);
        __syncthreads();
        {
            const float* u2p = U2s + j2;
            const float* hp  = Hs + b;
            #pragma unroll 8
            for (int k = 0; k < 128; k++) {
                ulonglong2 u = *(const ulonglong2*)(u2p);
                float h = *hp;
                unsigned long long hd = pk2(h, h);
                fma2(acc2[0], u.x, hd); fma2(acc2[1], u.y, hd);
                u2p += 32; hp += 32;
            }
        }
        CPA_WAIT(0);
        __syncthreads();
        {
            const float* u2p = U2s + 128 * 32 + j2;
            const float* hp  = Hs + 128 * 32 + b;
            #pragma unroll 8
            for (int k = 0; k < 128; k++) {
                ulonglong2 u = *(const ulonglong2*)(u2p);
                float h = *hp;
                unsigned long long hd = pk2(h, h);
                fma2(acc2[0], u.x, hd); fma2(acc2[1], u.y, hd);
                u2p += 32; hp += 32;
            }
        }

        // epilogue: gate combine, clip, write H (slot (s+1)&1), publish, then ci
        float* Hw = g_Hd + ((((s + 1) & 1) << 4) + gi) * 8192;
        float hn[4];
        {
            float w[4];
            up2(acc2[0], w[0], w[1]);
            up2(acc2[1], w[2], w[3]);
            #pragma unroll
            for (int j = 0; j < 4; j++) {
                int jl = j2 + j;
                float z  = Zs[jl * 32 + b];
                float ho = HsSv[jl * 32 + b];
                float cand = tanhfast(w[j]);
                float v = z * ho + (1.0f - z) * cand;
                hn[j] = fminf(5.0f, fmaxf(-5.0f, v));
                __stcg(Hw + (d0 + jl) * 32 + b, hn[j]);
            }
        }
        __syncthreads();
        if (tid == 0) {
            __threadfence();
            *((volatile unsigned*)&g_seq[gi * 8 + cs]) = sv + 2u;
        }
        if (g >= 2 && s < Tn - 1) {
            int Bg = pg * 32 + b;
            size_t row = (g == 2)
                ? ((size_t)Bg * Tn + s + 1) * 512 + d0 + j2
                : ((size_t)Bg * Tn + (Tn - 2 - s)) * 512 + 256 + d0 + j2;
            __stcg((float4*)(ci + row), make_float4(hn[0], hn[1], hn[2], hn[3]));
        }
    }

    // ================= fused heads (ic GRUs only) =================
    if (g < 2) {
        __syncthreads();
        if (tid == 0) {
            __threadfence();
            atomicAdd(&g_headbar, 1u);
            while (*((volatile unsigned*)&g_headbar) < 64u) { __nanosleep(64); }
            __threadfence();
        }
        __syncthreads();

        // final H lives in parity slot Tn&1 == 0 (first 131072 floats of g_Hd)
        int rank = g * 32 + pg * 8 + cs;
        int b0 = rank * 2;
        float* hn0 = U1s;
        for (int i = tid; i < 2 * 512; i += 256) {
            int bb = i >> 9, kk = i & 511;
            int bat = b0 + bb;
            int pgr = bat >> 5, b32 = bat & 31;
            float v = (kk < 256) ? g_Hd[pgr * 8192 + kk * 32 + b32]
                                 : g_Hd[(4 + pgr) * 8192 + (kk - 256) * 32 + b32];
            hn0[i] = v;
        }
        __syncthreads();
        int m  = tid & 127;
        int bb = tid >> 7;
        const float* hv = hn0 + bb * 512;
        float am = bm[m], alv = blv[m];
        for (int k = 0; k < 512; k++) {
            float h = hv[k];
            am  += h * Wm [k * 128 + m];
            alv += h * Wlv[k * 128 + m];
        }
        out[(b0 + bb) * 128 + m] = am;
        out[16384 + (b0 + bb) * 128 + m] = sqrtf(expf(alv) + 1e-4f);
    }
}

// ---------------- launch ----------------
extern "C" void kernel_launch(void* const* d_in, const int* in_sizes, int n_in,
                              void* d_out, int out_size) {
    const float* data = (const float*)d_in[0];
    const float* icWf = (const float*)d_in[1];
    const float* icUf = (const float*)d_in[2];
    const float* icbf = (const float*)d_in[3];
    const float* icWb = (const float*)d_in[4];
    const float* icUb = (const float*)d_in[5];
    const float* icbb = (const float*)d_in[6];
    const float* ich0 = (const float*)d_in[7];
    const float* ciWf = (const float*)d_in[8];
    const float* ciUf = (const float*)d_in[9];
    const float* cibf = (const float*)d_in[10];
    const float* ciWb = (const float*)d_in[11];
    const float* ciUb = (const float*)d_in[12];
    const float* cibb = (const float*)d_in[13];
    const float* cih0 = (const float*)d_in[14];
    const float* Wm   = (const float*)d_in[15];
    const float* bm   = (const float*)d_in[16];
    const float* Wlv  = (const float*)d_in[17];
    const float* blv  = (const float*)d_in[18];
    float* out = (float*)d_out;

    cudaFuncSetAttribute(scan_kernel, cudaFuncAttributeMaxDynamicSharedMemorySize,
                         SCAN_SMEM_BYTES);

    init_kernel<<<512, 256>>>(ich0, cih0, out);

    dim3 grid(24, Tn);
    xproj_kernel<<<grid, 256>>>(data, icWf, icWb, ciWf, ciWb,
                                icbf, icbb, cibf, cibb);

    scan_kernel<<<128, 256, SCAN_SMEM_BYTES>>>(icUf, icUb, ciUf, ciUb,
                                               Wm, bm, Wlv, blv, out);
}

// round 10
// speedup vs baseline: 1.2301x; 1.2301x over previous
#include <cuda_runtime.h>
#include <math.h>

#define Tn 1024
#define Bn 128

// ---------------- static device scratch ----------------
// g_XP[((t*4 + g)*768 + col)*128 + b]
__device__ float g_XP[(size_t)Bn * Tn * 3072];
__device__ float g_Hfin[8 * 8192];     // final H for ic GRUs: [gi][k][b32]
__device__ unsigned g_headbar;

// ---------------- f32x2 helpers ----------------
static __device__ __forceinline__ unsigned long long pk2(float lo, float hi) {
    unsigned long long r;
    asm("mov.b64 %0, {%1, %2};" : "=l"(r) : "f"(lo), "f"(hi));
    return r;
}
static __device__ __forceinline__ void up2(unsigned long long v, float& lo, float& hi) {
    asm("mov.b64 {%0, %1}, %2;" : "=f"(lo), "=f"(hi) : "l"(v));
}
static __device__ __forceinline__ void fma2(unsigned long long& d,
                                            unsigned long long a,
                                            unsigned long long b) {
    asm("fma.rn.f32x2 %0, %1, %2, %0;" : "+l"(d) : "l"(a), "l"(b));
}
static __device__ __forceinline__ float sigf(float x) {
    return 1.0f / (1.0f + __expf(-x));
}
static __device__ __forceinline__ float tanhfast(float x) {
    float e = __expf(2.0f * x);
    return 1.0f - 2.0f / (e + 1.0f);
}

// ---------------- cp.async helpers ----------------
static __device__ __forceinline__ void cpa16(void* smem, const void* gmem) {
    unsigned s = (unsigned)__cvta_generic_to_shared(smem);
    asm volatile("cp.async.cg.shared.global [%0], [%1], 16;" :: "r"(s), "l"(gmem));
}
#define CPA_COMMIT() asm volatile("cp.async.commit_group;")
#define CPA_WAIT(n)  asm volatile("cp.async.wait_group %0;" :: "n"(n))

// ---------------- cluster / mbarrier helpers ----------------
static __device__ __forceinline__ unsigned s2u(const void* p) {
    unsigned a;
    asm("{ .reg .u64 t; cvta.to.shared.u64 t, %1; cvt.u32.u64 %0, t; }" : "=r"(a) : "l"(p));
    return a;
}
static __device__ __forceinline__ unsigned mapa_u32(unsigned a, int r) {
    unsigned d;
    asm("mapa.shared::cluster.u32 %0, %1, %2;" : "=r"(d) : "r"(a), "r"(r));
    return d;
}
static __device__ __forceinline__ void bulk_peer(unsigned dst, unsigned src,
                                                 unsigned n, unsigned rbar) {
    asm volatile("cp.async.bulk.shared::cluster.shared::cta.mbarrier::complete_tx::bytes "
                 "[%0], [%1], %2, [%3];"
                 :: "r"(dst), "r"(src), "r"(n), "r"(rbar) : "memory");
}
#define MBAR_INIT(a, c) \
    asm volatile("mbarrier.init.shared.b64 [%0], %1;" :: "r"(a), "r"(c) : "memory")
#define MBAR_EXPECT(a, tx) \
    asm volatile("mbarrier.arrive.expect_tx.shared.b64 _, [%0], %1;" :: "r"(a), "r"(tx) : "memory")
#define FENCE_PA() asm volatile("fence.proxy.async.shared::cta;" ::: "memory")
#define CLUSTER_SYNC() do { \
    asm volatile("barrier.cluster.arrive.aligned;" ::: "memory"); \
    asm volatile("barrier.cluster.wait.aligned;" ::: "memory"); } while(0)

static __device__ __forceinline__ void waitp(unsigned bar, unsigned par) {
    asm volatile(
        "{\n\t.reg .pred P1;\n\t"
        "WL%=:\n\t"
        "mbarrier.try_wait.parity.acquire.cta.shared::cta.b64 P1, [%0], %1, 0x989680;\n\t"
        "@P1 bra.uni WD%=;\n\t"
        "bra.uni WL%=;\n\t"
        "WD%=:\n\t}"
        :: "r"(bar), "r"(par) : "memory");
}

// ---------------- init: ci boundary zeros + head barrier ----------------
__global__ void init_kernel(float* __restrict__ out) {
    int i = blockIdx.x * 256 + threadIdx.x;
    if (i < Bn * 256) {
        int b = i / 256, d = i % 256;
        float* ci = out + 32768;
        ci[((size_t)b * Tn) * 512 + d] = 0.0f;
        ci[((size_t)b * Tn + (Tn - 1)) * 512 + 256 + d] = 0.0f;
    }
    if (i == 0) g_headbar = 0u;
}

// ---------------- xproj SGEMM (f32x2, transposed output) ----------------
__global__ void __launch_bounds__(256) xproj_kernel(
    const float* __restrict__ X,
    const float* __restrict__ W0, const float* __restrict__ W1,
    const float* __restrict__ W2, const float* __restrict__ W3,
    const float* __restrict__ b0, const float* __restrict__ b1,
    const float* __restrict__ b2, const float* __restrict__ b3)
{
    __shared__ float As[8][128];
    __shared__ float Bs[8][128];

    const int t_  = blockIdx.y;
    const int n0  = blockIdx.x * 128;
    const int g   = n0 / 768;
    const int nc  = n0 - g * 768;
    const float* W    = (g == 0) ? W0 : (g == 1) ? W1 : (g == 2) ? W2 : W3;
    const float* bias = (g == 0) ? b0 : (g == 1) ? b1 : (g == 2) ? b2 : b3;

    const int tid  = threadIdx.x;
    const int warp = tid >> 5, lane = tid & 31;
    const int row0 = (warp & 3) * 32 + (lane >> 3) * 8;
    const int col0 = (warp >> 2) * 64 + (lane & 7) * 8;

    const int am = tid >> 1, ak = (tid & 1) * 4;
    const int bk = tid >> 5, bn = (tid & 31) * 4;

    unsigned long long acc[8][4];
    #pragma unroll
    for (int i = 0; i < 8; i++)
        #pragma unroll
        for (int j = 0; j < 4; j++) acc[i][j] = 0ULL;

    for (int k0 = 0; k0 < 256; k0 += 8) {
        float4 av = __ldg((const float4*)&X[(size_t)am * (Tn * 256) + t_ * 256 + k0 + ak]);
        float4 bv = __ldg((const float4*)&W[(size_t)(k0 + bk) * 768 + nc + bn]);
        __syncthreads();
        As[ak + 0][am] = av.x; As[ak + 1][am] = av.y;
        As[ak + 2][am] = av.z; As[ak + 3][am] = av.w;
        *(float4*)&Bs[bk][bn] = bv;
        __syncthreads();

        #pragma unroll
        for (int kk = 0; kk < 8; ++kk) {
            float4 a0 = *(const float4*)&As[kk][row0];
            float4 a1 = *(const float4*)&As[kk][row0 + 4];
            ulonglong2 b01 = *(const ulonglong2*)&Bs[kk][col0];
            ulonglong2 b23 = *(const ulonglong2*)&Bs[kk][col0 + 4];
            float ar[8] = {a0.x, a0.y, a0.z, a0.w, a1.x, a1.y, a1.z, a1.w};
            #pragma unroll
            for (int i = 0; i < 8; i++) {
                unsigned long long ai = pk2(ar[i], ar[i]);
                fma2(acc[i][0], ai, b01.x);
                fma2(acc[i][1], ai, b01.y);
                fma2(acc[i][2], ai, b23.x);
                fma2(acc[i][3], ai, b23.y);
            }
        }
    }

    float c[8][8];
    #pragma unroll
    for (int i = 0; i < 8; i++) {
        up2(acc[i][0], c[i][0], c[i][1]);
        up2(acc[i][1], c[i][2], c[i][3]);
        up2(acc[i][2], c[i][4], c[i][5]);
        up2(acc[i][3], c[i][6], c[i][7]);
    }
    #pragma unroll
    for (int j = 0; j < 8; j++) {
        float bb = bias[nc + col0 + j];
        size_t base = ((size_t)(t_ * 4 + g) * 768 + nc + col0 + j) * 128 + row0;
        float4 v0 = make_float4(c[0][j] + bb, c[1][j] + bb, c[2][j] + bb, c[3][j] + bb);
        float4 v1 = make_float4(c[4][j] + bb, c[5][j] + bb, c[6][j] + bb, c[7][j] + bb);
        __stcg((float4*)&g_XP[base],     v0);
        __stcg((float4*)&g_XP[base + 4], v1);
    }
}

// ---------------- scan smem layout (floats) ----------------
#define HB0  0                // 8192 : H buffer parity 0  [256][32]
#define HB1  8192             // 8192 : H buffer parity 1
#define RHO  16384            // 8192 : RH buffer [256][32]
#define U1O  24576            // 16384: zr U slab [256][64]
#define U2O  40960            // 8192 : hh U slab [256][32]
#define XPO  49152            // 6144 : XP double buffer [2][96][32]
#define ZSO  55296            // 1024 : z gate [32][32]
#define BARO 56320            // 4    : 2 mbarriers (u64 each)
#define SMEM_FLOATS 56328
#define SMEM_BYTES  (SMEM_FLOATS * 4)   // 225312

#define EXPECT_TX 28672u      // 7 peers x 4096 B

// ---------------- persistent scan: 128 CTAs = 16 clusters of 8 ----------------
__global__ void __launch_bounds__(256, 1) scan_kernel(
    const float* __restrict__ U0, const float* __restrict__ U1,
    const float* __restrict__ U2, const float* __restrict__ U3,
    const float* __restrict__ ich0, const float* __restrict__ cih0,
    const float* __restrict__ Wm, const float* __restrict__ bm,
    const float* __restrict__ Wlv, const float* __restrict__ blv,
    float* __restrict__ out)
{
    extern __shared__ float sm[];
    float* U1s = sm + U1O;
    float* U2s = sm + U2O;
    float* XPd = sm + XPO;
    float* Zs  = sm + ZSO;
    float* RHs = sm + RHO;

    const int g   = blockIdx.x >> 5;
    const int pg  = (blockIdx.x >> 3) & 3;
    const int cs  = blockIdx.x & 7;        // == cluster rank
    const int d0  = cs * 32;
    const int gi  = g * 4 + pg;
    const int tid = threadIdx.x;
    const int b   = tid & 31;
    const int jo  = tid >> 5;
    const float* U  = (g == 0) ? U0 : (g == 1) ? U1 : (g == 2) ? U2 : U3;
    const float* h0 = (g < 2) ? ich0 : cih0;

    const unsigned smem_base = s2u(sm);
    const unsigned rh_bar = smem_base + BARO * 4;
    const unsigned h_bar  = rh_bar + 8;

    if (tid == 0) { MBAR_INIT(rh_bar, 1); MBAR_INIT(h_bar, 1); }

    // H0 into parity-0 buffer (identical in all CTAs of the cluster)
    for (int i = tid; i < 8192; i += 256)
        sm[HB0 + i] = h0[(g & 1) * 256 + (i >> 5)];

    // resident U slabs
    for (int i = tid; i < 256 * 64; i += 256) {
        int k = i >> 6, jj = i & 63;
        int col = (jj < 32) ? (d0 + jj) : (256 + d0 + jj - 32);
        U1s[i] = U[k * 768 + col];
    }
    for (int i = tid; i < 256 * 32; i += 256) {
        int k = i >> 5, jj = i & 31;
        U2s[i] = U[k * 768 + 512 + d0 + jj];
    }

    // stage XP(0)
    {
        int t0 = (g & 1) ? (Tn - 1) : 0;
        const float* xpb = g_XP + ((size_t)t0 * 4 + g) * 98304;
        #pragma unroll
        for (int i = 0; i < 3; i++) {
            int idx = i * 256 + tid;
            int cl = idx >> 3, seg = idx & 7;
            int gcol = (cl < 32) ? (d0 + cl) : (cl < 64) ? (256 + d0 + cl - 32)
                                             : (512 + d0 + cl - 64);
            cpa16(XPd + cl * 32 + seg * 4, xpb + gcol * 128 + pg * 32 + seg * 4);
        }
        CPA_COMMIT();
        CPA_WAIT(0);
    }
    __syncthreads();
    CLUSTER_SYNC();   // all peers' mbarriers + buffers ready before any remote op

    // precompute peer ranks and remote barrier addresses (tid < 7)
    int pr = 0;
    unsigned rb_rh = 0, rb_h = 0;
    if (tid < 7) {
        pr = tid + (tid >= cs ? 1 : 0);
        rb_rh = mapa_u32(rh_bar, pr);
        rb_h  = mapa_u32(h_bar, pr);
    }

    const int j1 = jo * 8;
    const int j2 = jo * 4;
    float* ci = out + 32768;

    for (int s = 0; s < Tn; s++) {
        const float* XPc = XPd + (s & 1) * 3072;
        float* Hcur  = sm + ((s & 1) ? HB1 : HB0);
        float* Hnext = sm + ((s & 1) ? HB0 : HB1);

        if (tid == 0) MBAR_EXPECT(rh_bar, EXPECT_TX);

        // prefetch XP(s+1)
        {
            int sn = (s < Tn - 1) ? (s + 1) : s;
            int tn_ = (g & 1) ? (Tn - 1 - sn) : sn;
            const float* xpb = g_XP + ((size_t)tn_ * 4 + g) * 98304;
            float* dst = XPd + ((s + 1) & 1) * 3072;
            #pragma unroll
            for (int i = 0; i < 3; i++) {
                int idx = i * 256 + tid;
                int cl = idx >> 3, seg = idx & 7;
                int gcol = (cl < 32) ? (d0 + cl) : (cl < 64) ? (256 + d0 + cl - 32)
                                                 : (512 + d0 + cl - 64);
                cpa16(dst + cl * 32 + seg * 4, xpb + gcol * 128 + pg * 32 + seg * 4);
            }
            CPA_COMMIT();
        }

        // wait H(s) (landed in Hcur via peers' bulk pushes); s=0 is local init
        if (s > 0) waitp(h_bar, (s & 1) ^ 1);
        if (tid == 0) MBAR_EXPECT(h_bar, EXPECT_TX);

        CPA_WAIT(1);
        __syncthreads();

        // ---- phase 1: zr pre-activation ----
        unsigned long long acc[4];
        #pragma unroll
        for (int p = 0; p < 4; p++)
            acc[p] = pk2(XPc[(j1 + 2 * p) * 32 + b], XPc[(j1 + 2 * p + 1) * 32 + b]);
        {
            const float* u1p = U1s + j1;
            const float* hp  = Hcur + b;
            #pragma unroll 8
            for (int k = 0; k < 256; k++) {
                ulonglong2 ua = *(const ulonglong2*)(u1p);
                ulonglong2 ub = *(const ulonglong2*)(u1p + 4);
                float h = *hp;
                unsigned long long hd = pk2(h, h);
                fma2(acc[0], ua.x, hd); fma2(acc[1], ua.y, hd);
                fma2(acc[2], ub.x, hd); fma2(acc[3], ub.y, hd);
                u1p += 64; hp += 32;
            }
        }
        // epilogue: z -> Zs, r -> rh -> own RHs slice
        {
            float v[8];
            #pragma unroll
            for (int p = 0; p < 4; p++) up2(acc[p], v[2 * p], v[2 * p + 1]);
            if (jo < 4) {
                #pragma unroll
                for (int j = 0; j < 8; j++)
                    Zs[(j1 + j) * 32 + b] = sigf(v[j]);
            } else {
                int jb = (jo - 4) * 8;
                #pragma unroll
                for (int j = 0; j < 8; j++) {
                    int d = d0 + jb + j;
                    RHs[d * 32 + b] = sigf(v[j]) * Hcur[d * 32 + b];
                }
            }
        }
        __syncthreads();
        if (tid < 7) {
            FENCE_PA();
            unsigned src = smem_base + (RHO + d0 * 32) * 4;
            bulk_peer(mapa_u32(src, pr), src, 4096u, rb_rh);
        }
        // wait all 8 RH slices (7 remote + own local)
        waitp(rh_bar, s & 1);

        // ---- phase 2: candidate + update ----
        unsigned long long acc2[2];
        #pragma unroll
        for (int p = 0; p < 2; p++)
            acc2[p] = pk2(XPc[(64 + j2 + 2 * p) * 32 + b],
                          XPc[(64 + j2 + 2 * p + 1) * 32 + b]);
        {
            const float* u2p = U2s + j2;
            const float* hp  = RHs + b;
            #pragma unroll 8
            for (int k = 0; k < 256; k++) {
                ulonglong2 u = *(const ulonglong2*)(u2p);
                float h = *hp;
                unsigned long long hd = pk2(h, h);
                fma2(acc2[0], u.x, hd); fma2(acc2[1], u.y, hd);
                u2p += 32; hp += 32;
            }
        }
        // epilogue: gate combine, clip, write own Hnext slice, outputs
        {
            float w[4], hn[4];
            up2(acc2[0], w[0], w[1]);
            up2(acc2[1], w[2], w[3]);
            #pragma unroll
            for (int j = 0; j < 4; j++) {
                int jl = j2 + j;
                int d  = d0 + jl;
                float z  = Zs[jl * 32 + b];
                float ho = Hcur[d * 32 + b];
                float cand = tanhfast(w[j]);
                float v = z * ho + (1.0f - z) * cand;
                hn[j] = fminf(5.0f, fmaxf(-5.0f, v));
                Hnext[d * 32 + b] = hn[j];
            }
            if (g >= 2 && s < Tn - 1) {
                int Bg = pg * 32 + b;
                size_t row = (g == 2)
                    ? ((size_t)Bg * Tn + s + 1) * 512 + d0 + j2
                    : ((size_t)Bg * Tn + (Tn - 2 - s)) * 512 + 256 + d0 + j2;
                __stcg((float4*)(ci + row), make_float4(hn[0], hn[1], hn[2], hn[3]));
            }
            if (g < 2 && s == Tn - 1) {
                #pragma unroll
                for (int j = 0; j < 4; j++)
                    __stcg(g_Hfin + gi * 8192 + (d0 + j2 + j) * 32 + b, hn[j]);
            }
        }
        __syncthreads();
        if (tid < 7 && s < Tn - 1) {
            FENCE_PA();
            unsigned src = smem_base + (((s & 1) ? HB0 : HB1) + d0 * 32) * 4;
            bulk_peer(mapa_u32(src, pr), src, 4096u, rb_h);
        }
    }

    CLUSTER_SYNC();   // no CTA exits while peer bulks may still touch its smem

    // ================= fused heads (ic GRUs only) =================
    if (g < 2) {
        __syncthreads();
        if (tid == 0) {
            __threadfence();
            atomicAdd(&g_headbar, 1u);
            while (*((volatile unsigned*)&g_headbar) < 64u) { __nanosleep(64); }
            __threadfence();
        }
        __syncthreads();

        int rank = g * 32 + pg * 8 + cs;      // 0..63
        int b0 = rank * 2;
        float* hn0 = U1s;
        for (int i = tid; i < 2 * 512; i += 256) {
            int bb = i >> 9, kk = i & 511;
            int bat = b0 + bb;
            int pgr = bat >> 5, b32 = bat & 31;
            float v = (kk < 256) ? g_Hfin[pgr * 8192 + kk * 32 + b32]
                                 : g_Hfin[(4 + pgr) * 8192 + (kk - 256) * 32 + b32];
            hn0[i] = v;
        }
        __syncthreads();
        int m  = tid & 127;
        int bb = tid >> 7;
        const float* hv = hn0 + bb * 512;
        float am = bm[m], alv = blv[m];
        for (int k = 0; k < 512; k++) {
            float h = hv[k];
            am  += h * Wm [k * 128 + m];
            alv += h * Wlv[k * 128 + m];
        }
        out[(b0 + bb) * 128 + m] = am;
        out[16384 + (b0 + bb) * 128 + m] = sqrtf(expf(alv) + 1e-4f);
    }
}

// ---------------- launch ----------------
extern "C" void kernel_launch(void* const* d_in, const int* in_sizes, int n_in,
                              void* d_out, int out_size) {
    const float* data = (const float*)d_in[0];
    const float* icWf = (const float*)d_in[1];
    const float* icUf = (const float*)d_in[2];
    const float* icbf = (const float*)d_in[3];
    const float* icWb = (const float*)d_in[4];
    const float* icUb = (const float*)d_in[5];
    const float* icbb = (const float*)d_in[6];
    const float* ich0 = (const float*)d_in[7];
    const float* ciWf = (const float*)d_in[8];
    const float* ciUf = (const float*)d_in[9];
    const float* cibf = (const float*)d_in[10];
    const float* ciWb = (const float*)d_in[11];
    const float* ciUb = (const float*)d_in[12];
    const float* cibb = (const float*)d_in[13];
    const float* cih0 = (const float*)d_in[14];
    const float* Wm   = (const float*)d_in[15];
    const float* bm   = (const float*)d_in[16];
    const float* Wlv  = (const float*)d_in[17];
    const float* blv  = (const float*)d_in[18];
    float* out = (float*)d_out;

    cudaFuncSetAttribute(scan_kernel, cudaFuncAttributeMaxDynamicSharedMemorySize,
                         SMEM_BYTES);

    init_kernel<<<128, 256>>>(out);

    dim3 grid(24, Tn);
    xproj_kernel<<<grid, 256>>>(data, icWf, icWb, ciWf, ciWb,
                                icbf, icbb, cibf, cibb);

    cudaLaunchConfig_t cfg = {};
    cfg.gridDim = dim3(128, 1, 1);
    cfg.blockDim = dim3(256, 1, 1);
    cfg.dynamicSmemBytes = SMEM_BYTES;
    cfg.stream = 0;
    cudaLaunchAttribute attrs[1];
    attrs[0].id = cudaLaunchAttributeClusterDimension;
    attrs[0].val.clusterDim.x = 8;
    attrs[0].val.clusterDim.y = 1;
    attrs[0].val.clusterDim.z = 1;
    cfg.attrs = attrs;
    cfg.numAttrs = 1;
    cudaLaunchKernelEx(&cfg, scan_kernel,
                       icUf, icUb, ciUf, ciUb, ich0, cih0,
                       Wm, bm, Wlv, blv, out);
}

// round 11
// speedup vs baseline: 1.7859x; 1.4518x over previous
#include <cuda_runtime.h>
#include <math.h>

#define Tn 1024
#define Bn 128
#define Nn 256
#define Dn 256

// ---------------- static device scratch ----------------
// g_XP[((t*4 + g)*768 + col)*128 + b]
__device__ float g_XP[(size_t)Bn * Tn * 3072];
// g_H / g_RH: [(g*4 + pgroup)*256 + k]*32 + b32   (batch-group-sliced)
__device__ float g_H [16 * 256 * 32];
__device__ float g_RH[16 * 256 * 32];
__device__ unsigned g_bar[17];     // [0..15]: scan groups, [16]: head barrier

// ---------------- f32x2 helpers ----------------
static __device__ __forceinline__ unsigned long long pk2(float lo, float hi) {
    unsigned long long r;
    asm("mov.b64 %0, {%1, %2};" : "=l"(r) : "f"(lo), "f"(hi));
    return r;
}
static __device__ __forceinline__ void up2(unsigned long long v, float& lo, float& hi) {
    asm("mov.b64 {%0, %1}, %2;" : "=f"(lo), "=f"(hi) : "l"(v));
}
static __device__ __forceinline__ void fma2(unsigned long long& d,
                                            unsigned long long a,
                                            unsigned long long b) {
    asm("fma.rn.f32x2 %0, %1, %2, %0;" : "+l"(d) : "l"(a), "l"(b));
}
static __device__ __forceinline__ float sigf(float x) {
    return 1.0f / (1.0f + __expf(-x));
}
static __device__ __forceinline__ float tanhfast(float x) {
    float e = __expf(2.0f * x);
    return 1.0f - 2.0f / (e + 1.0f);
}

// ---------------- cp.async helpers ----------------
static __device__ __forceinline__ void cpa16(void* smem, const void* gmem) {
    unsigned s = (unsigned)__cvta_generic_to_shared(smem);
    asm volatile("cp.async.cg.shared.global [%0], [%1], 16;" :: "r"(s), "l"(gmem));
}
#define CPA_COMMIT() asm volatile("cp.async.commit_group;")
#define CPA_WAIT(n)  asm volatile("cp.async.wait_group %0;" :: "n"(n))

// ---------------- xproj SGEMM (f32x2, transposed output) + folded init ----------------
__global__ void __launch_bounds__(256) xproj_kernel(
    const float* __restrict__ X,
    const float* __restrict__ W0, const float* __restrict__ W1,
    const float* __restrict__ W2, const float* __restrict__ W3,
    const float* __restrict__ b0, const float* __restrict__ b1,
    const float* __restrict__ b2, const float* __restrict__ b3,
    const float* __restrict__ ich0, const float* __restrict__ cih0,
    float* __restrict__ out)
{
    __shared__ float As[8][128];
    __shared__ float Bs[8][128];

    const int t_  = blockIdx.y;
    const int n0  = blockIdx.x * 128;
    const int g   = n0 / 768;
    const int nc  = n0 - g * 768;
    const float* W    = (g == 0) ? W0 : (g == 1) ? W1 : (g == 2) ? W2 : W3;
    const float* bias = (g == 0) ? b0 : (g == 1) ? b1 : (g == 2) ? b2 : b3;

    const int tid  = threadIdx.x;
    const int warp = tid >> 5, lane = tid & 31;
    const int row0 = (warp & 3) * 32 + (lane >> 3) * 8;
    const int col0 = (warp >> 2) * 64 + (lane & 7) * 8;

    const int am = tid >> 1, ak = (tid & 1) * 4;
    const int bk = tid >> 5, bn = (tid & 31) * 4;

    // ---- folded init (24 blocks with t_==0) ----
    if (t_ == 0) {
        float* ci = out + 32768;
        for (int i = blockIdx.x * 256 + tid; i < Bn * Dn; i += 24 * 256) {
            int b = i >> 8, d = i & 255;
            ci[((size_t)b * Tn) * 512 + d] = 0.0f;
            ci[((size_t)b * Tn + (Tn - 1)) * 512 + 256 + d] = 0.0f;
        }
        if (blockIdx.x == 0 && tid < 17) g_bar[tid] = 0u;
        // H0 init: g_H[gi][k][b32]
        for (int i = blockIdx.x * 256 + tid; i < 16 * 8192; i += 24 * 256) {
            int gi = i >> 13;
            int gg = gi >> 2;
            int k  = (i >> 5) & 255;
            const float* h0 = (gg < 2) ? ich0 : cih0;
            g_H[i] = h0[(gg & 1) * Dn + k];
        }
    }

    unsigned long long acc[8][4];
    #pragma unroll
    for (int i = 0; i < 8; i++)
        #pragma unroll
        for (int j = 0; j < 4; j++) acc[i][j] = 0ULL;

    for (int k0 = 0; k0 < 256; k0 += 8) {
        float4 av = __ldg((const float4*)&X[(size_t)am * (Tn * 256) + t_ * 256 + k0 + ak]);
        float4 bv = __ldg((const float4*)&W[(size_t)(k0 + bk) * 768 + nc + bn]);
        __syncthreads();
        As[ak + 0][am] = av.x; As[ak + 1][am] = av.y;
        As[ak + 2][am] = av.z; As[ak + 3][am] = av.w;
        *(float4*)&Bs[bk][bn] = bv;
        __syncthreads();

        #pragma unroll
        for (int kk = 0; kk < 8; ++kk) {
            float4 a0 = *(const float4*)&As[kk][row0];
            float4 a1 = *(const float4*)&As[kk][row0 + 4];
            ulonglong2 b01 = *(const ulonglong2*)&Bs[kk][col0];
            ulonglong2 b23 = *(const ulonglong2*)&Bs[kk][col0 + 4];
            float ar[8] = {a0.x, a0.y, a0.z, a0.w, a1.x, a1.y, a1.z, a1.w};
            #pragma unroll
            for (int i = 0; i < 8; i++) {
                unsigned long long ai = pk2(ar[i], ar[i]);
                fma2(acc[i][0], ai, b01.x);
                fma2(acc[i][1], ai, b01.y);
                fma2(acc[i][2], ai, b23.x);
                fma2(acc[i][3], ai, b23.y);
            }
        }
    }

    float c[8][8];
    #pragma unroll
    for (int i = 0; i < 8; i++) {
        up2(acc[i][0], c[i][0], c[i][1]);
        up2(acc[i][1], c[i][2], c[i][3]);
        up2(acc[i][2], c[i][4], c[i][5]);
        up2(acc[i][3], c[i][6], c[i][7]);
    }
    #pragma unroll
    for (int j = 0; j < 8; j++) {
        float bb = bias[nc + col0 + j];
        size_t base = ((size_t)(t_ * 4 + g) * 768 + nc + col0 + j) * 128 + row0;
        float4 v0 = make_float4(c[0][j] + bb, c[1][j] + bb, c[2][j] + bb, c[3][j] + bb);
        float4 v1 = make_float4(c[4][j] + bb, c[5][j] + bb, c[6][j] + bb, c[7][j] + bb);
        __stcg((float4*)&g_XP[base],     v0);
        __stcg((float4*)&g_XP[base + 4], v1);
    }
}

// ---------------- grid barrier (cumulative release via thread0 fence) ----------------
static __device__ __forceinline__ void gbar(int gi, unsigned target) {
    __syncthreads();
    if (threadIdx.x == 0) {
        __threadfence();
        atomicAdd(&g_bar[gi], 1u);
        while (*((volatile unsigned*)&g_bar[gi]) < target) { __nanosleep(32); }
        __threadfence();
    }
    __syncthreads();
}

// ---------------- scan smem layout (floats) ----------------
#define HS_OFF   0                        // 8192  : H/RH batch-slice [256][32]
#define U1_OFF   8192                     // 16384 : zr U slab [256][64]
#define U2_OFF   (U1_OFF + 16384)         // 8192  : hh U slab [256][32]
#define XP_OFF   (U2_OFF + 8192)          // 6144  : XP double buffer [2][96][32]
#define ZS_OFF   (XP_OFF + 6144)          // 1024  : z gate [32][32]
#define HSV_OFF  (ZS_OFF + 1024)          // 1024  : saved old-H [32][32]
#define SCAN_SMEM_FLOATS (HSV_OFF + 1024)
#define SCAN_SMEM_BYTES  (SCAN_SMEM_FLOATS * 4)   // 163840 B

// ---------------- persistent scan: 128 CTAs = 4 GRU x 4 bgroup x 8 colslice ----------------
__global__ void __launch_bounds__(256, 1) scan_kernel(
    const float* __restrict__ U0, const float* __restrict__ U1,
    const float* __restrict__ U2, const float* __restrict__ U3,
    const float* __restrict__ Wm, const float* __restrict__ bm,
    const float* __restrict__ Wlv, const float* __restrict__ blv,
    float* __restrict__ out)
{
    extern __shared__ float sm[];
    float* Hs   = sm + HS_OFF;
    float* U1s  = sm + U1_OFF;
    float* U2s  = sm + U2_OFF;
    float* XPd  = sm + XP_OFF;
    float* Zs   = sm + ZS_OFF;
    float* HsSv = sm + HSV_OFF;

    const int g   = blockIdx.x >> 5;
    const int pg  = (blockIdx.x >> 3) & 3;
    const int cs  = blockIdx.x & 7;
    const int d0  = cs * 32;
    const int gi  = g * 4 + pg;
    const int tid = threadIdx.x;
    const int b   = tid & 31;
    const int jo  = tid >> 5;
    const float* U = (g == 0) ? U0 : (g == 1) ? U1 : (g == 2) ? U2 : U3;

    // resident U slabs
    for (int i = tid; i < 256 * 64; i += 256) {
        int k = i >> 6, jj = i & 63;
        int col = (jj < 32) ? (d0 + jj) : (256 + d0 + jj - 32);
        U1s[i] = U[k * 768 + col];
    }
    for (int i = tid; i < 256 * 32; i += 256) {
        int k = i >> 5, jj = i & 31;
        U2s[i] = U[k * 768 + 512 + d0 + jj];
    }

    float* myH  = g_H  + gi * 8192;
    float* myRH = g_RH + gi * 8192;
    float* ci   = out + 32768;
    unsigned tgt = 0;

    const int j1 = jo * 8;
    const int j2 = jo * 4;

    // ---- prologue: stage H + XP(0) ----
    #pragma unroll
    for (int ch = 0; ch < 2; ch++) {
        #pragma unroll
        for (int r = 0; r < 4; r++)
            cpa16(Hs + ch * 4096 + (r * 256 + tid) * 4,
                  myH + ch * 4096 + (r * 256 + tid) * 4);
        CPA_COMMIT();
    }
    {
        int t0 = (g & 1) ? (Tn - 1) : 0;
        const float* xpb = g_XP + ((size_t)t0 * 4 + g) * 98304;
        #pragma unroll
        for (int i = 0; i < 3; i++) {
            int idx = i * 256 + tid;
            int cl = idx >> 3, seg = idx & 7;
            int gcol = (cl < 32) ? (d0 + cl) : (cl < 64) ? (256 + d0 + cl - 32)
                                             : (512 + d0 + cl - 64);
            cpa16(XPd + cl * 32 + seg * 4, xpb + gcol * 128 + pg * 32 + seg * 4);
        }
        CPA_COMMIT();
    }
    CPA_WAIT(0);
    __syncthreads();

    for (int s = 0; s < Tn; s++) {
        const float* XPc = XPd + (s & 1) * 3072;

        // ---- prefetch XP(s+1) ----
        {
            int sn = (s < Tn - 1) ? (s + 1) : s;
            int tn_ = (g & 1) ? (Tn - 1 - sn) : sn;
            const float* xpb = g_XP + ((size_t)tn_ * 4 + g) * 98304;
            float* dst = XPd + ((s + 1) & 1) * 3072;
            #pragma unroll
            for (int i = 0; i < 3; i++) {
                int idx = i * 256 + tid;
                int cl = idx >> 3, seg = idx & 7;
                int gcol = (cl < 32) ? (d0 + cl) : (cl < 64) ? (256 + d0 + cl - 32)
                                                 : (512 + d0 + cl - 64);
                cpa16(dst + cl * 32 + seg * 4, xpb + gcol * 128 + pg * 32 + seg * 4);
            }
            CPA_COMMIT();
        }

        // ---- phase 1: zr pre-activation ----
        unsigned long long acc[4];
        #pragma unroll
        for (int p = 0; p < 4; p++)
            acc[p] = pk2(XPc[(j1 + 2 * p) * 32 + b], XPc[(j1 + 2 * p + 1) * 32 + b]);

        CPA_WAIT(1);
        __syncthreads();
        {
            const float* u1p = U1s + j1;
            const float* hp  = Hs + b;
            #pragma unroll 8
            for (int k = 0; k < 128; k++) {
                ulonglong2 ua = *(const ulonglong2*)(u1p);
                ulonglong2 ub = *(const ulonglong2*)(u1p + 4);
                float h = *hp;
                unsigned long long hd = pk2(h, h);
                fma2(acc[0], ua.x, hd); fma2(acc[1], ua.y, hd);
                fma2(acc[2], ub.x, hd); fma2(acc[3], ub.y, hd);
                u1p += 64; hp += 32;
            }
        }
        CPA_WAIT(0);
        __syncthreads();
        {
            const float* u1p = U1s + 128 * 64 + j1;
            const float* hp  = Hs + 128 * 32 + b;
            #pragma unroll 8
            for (int k = 0; k < 128; k++) {
                ulonglong2 ua = *(const ulonglong2*)(u1p);
                ulonglong2 ub = *(const ulonglong2*)(u1p + 4);
                float h = *hp;
                unsigned long long hd = pk2(h, h);
                fma2(acc[0], ua.x, hd); fma2(acc[1], ua.y, hd);
                fma2(acc[2], ub.x, hd); fma2(acc[3], ub.y, hd);
                u1p += 64; hp += 32;
            }
        }

        // epilogue
        {
            float v[8];
            #pragma unroll
            for (int p = 0; p < 4; p++) up2(acc[p], v[2 * p], v[2 * p + 1]);
            if (jo < 4) {
                #pragma unroll
                for (int j = 0; j < 8; j++)
                    Zs[(j1 + j) * 32 + b] = sigf(v[j]);
            } else {
                int jb = j1 - 32;
                #pragma unroll
                for (int j = 0; j < 8; j++) {
                    int d = d0 + jb + j;
                    float rh = sigf(v[j]) * Hs[d * 32 + b];
                    __stcg(myRH + d * 32 + b, rh);
                }
            }
            float4 hv = *(const float4*)(Hs + d0 * 32 + tid * 4);
            *(float4*)(HsSv + tid * 4) = hv;
        }
        tgt += 8;
        gbar(gi, tgt);

        // ---- stage RH (2 chunks) ----
        #pragma unroll
        for (int ch = 0; ch < 2; ch++) {
            #pragma unroll
            for (int r = 0; r < 4; r++)
                cpa16(Hs + ch * 4096 + (r * 256 + tid) * 4,
                      myRH + ch * 4096 + (r * 256 + tid) * 4);
            CPA_COMMIT();
        }

        // ---- phase 2: candidate + update ----
        unsigned long long acc2[2];
        #pragma unroll
        for (int p = 0; p < 2; p++)
            acc2[p] = pk2(XPc[(64 + j2 + 2 * p) * 32 + b],
                          XPc[(64 + j2 + 2 * p + 1) * 32 + b]);

        CPA_WAIT(1);
        __syncthreads();
        {
            const float* u2p = U2s + j2;
            const float* hp  = Hs + b;
            #pragma unroll 8
            for (int k = 0; k < 128; k++) {
                ulonglong2 u = *(const ulonglong2*)(u2p);
                float h = *hp;
                unsigned long long hd = pk2(h, h);
                fma2(acc2[0], u.x, hd); fma2(acc2[1], u.y, hd);
                u2p += 32; hp += 32;
            }
        }
        CPA_WAIT(0);
        __syncthreads();
        {
            const float* u2p = U2s + 128 * 32 + j2;
            const float* hp  = Hs + 128 * 32 + b;
            #pragma unroll 8
            for (int k = 0; k < 128; k++) {
                ulonglong2 u = *(const ulonglong2*)(u2p);
                float h = *hp;
                unsigned long long hd = pk2(h, h);
                fma2(acc2[0], u.x, hd); fma2(acc2[1], u.y, hd);
                u2p += 32; hp += 32;
            }
        }

        // epilogue: gate combine, clip, write H; ci stores moved AFTER the barrier
        float hn[4];
        {
            float w[4];
            up2(acc2[0], w[0], w[1]);
            up2(acc2[1], w[2], w[3]);
            #pragma unroll
            for (int j = 0; j < 4; j++) {
                int jl = j2 + j;
                float z  = Zs[jl * 32 + b];
                float ho = HsSv[jl * 32 + b];
                float cand = tanhfast(w[j]);
                float v = z * ho + (1.0f - z) * cand;
                hn[j] = fminf(5.0f, fmaxf(-5.0f, v));
                __stcg(myH + (d0 + jl) * 32 + b, hn[j]);
            }
        }
        tgt += 8;
        gbar(gi, tgt);

        // ci outputs off the fenced path
        if (g >= 2 && s < Tn - 1) {
            int Bg = pg * 32 + b;
            size_t row = (g == 2)
                ? ((size_t)Bg * Tn + s + 1) * 512 + d0 + j2
                : ((size_t)Bg * Tn + (Tn - 2 - s)) * 512 + 256 + d0 + j2;
            __stcg((float4*)(ci + row), make_float4(hn[0], hn[1], hn[2], hn[3]));
        }

        // ---- stage H for next step ----
        if (s < Tn - 1) {
            #pragma unroll
            for (int ch = 0; ch < 2; ch++) {
                #pragma unroll
                for (int r = 0; r < 4; r++)
                    cpa16(Hs + ch * 4096 + (r * 256 + tid) * 4,
                          myH + ch * 4096 + (r * 256 + tid) * 4);
                CPA_COMMIT();
            }
        }
    }

    // ================= fused heads (ic GRUs only) =================
    if (g < 2) {
        __syncthreads();
        if (tid == 0) {
            __threadfence();
            atomicAdd(&g_bar[16], 1u);
            while (*((volatile unsigned*)&g_bar[16]) < 64u) { __nanosleep(64); }
            __threadfence();
        }
        __syncthreads();

        int rank = g * 32 + pg * 8 + cs;
        int b0 = rank * 2;
        float* hn0 = U1s;
        for (int i = tid; i < 2 * 512; i += 256) {
            int bb = i >> 9, kk = i & 511;
            int bat = b0 + bb;
            int pgr = bat >> 5, b32 = bat & 31;
            float v = (kk < 256) ? g_H[pgr * 8192 + kk * 32 + b32]
                                 : g_H[(4 + pgr) * 8192 + (kk - 256) * 32 + b32];
            hn0[i] = v;
        }
        __syncthreads();
        int m  = tid & 127;
        int bb = tid >> 7;
        const float* hv = hn0 + bb * 512;
        float am = bm[m], alv = blv[m];
        for (int k = 0; k < 512; k++) {
            float h = hv[k];
            am  += h * Wm [k * 128 + m];
            alv += h * Wlv[k * 128 + m];
        }
        out[(b0 + bb) * 128 + m] = am;
        out[16384 + (b0 + bb) * 128 + m] = sqrtf(expf(alv) + 1e-4f);
    }
}

// ---------------- launch (2 kernels -> ncu #6 lands on scan) ----------------
extern "C" void kernel_launch(void* const* d_in, const int* in_sizes, int n_in,
                              void* d_out, int out_size) {
    const float* data = (const float*)d_in[0];
    const float* icWf = (const float*)d_in[1];
    const float* icUf = (const float*)d_in[2];
    const float* icbf = (const float*)d_in[3];
    const float* icWb = (const float*)d_in[4];
    const float* icUb = (const float*)d_in[5];
    const float* icbb = (const float*)d_in[6];
    const float* ich0 = (const float*)d_in[7];
    const float* ciWf = (const float*)d_in[8];
    const float* ciUf = (const float*)d_in[9];
    const float* cibf = (const float*)d_in[10];
    const float* ciWb = (const float*)d_in[11];
    const float* ciUb = (const float*)d_in[12];
    const float* cibb = (const float*)d_in[13];
    const float* cih0 = (const float*)d_in[14];
    const float* Wm   = (const float*)d_in[15];
    const float* bm   = (const float*)d_in[16];
    const float* Wlv  = (const float*)d_in[17];
    const float* blv  = (const float*)d_in[18];
    float* out = (float*)d_out;

    cudaFuncSetAttribute(scan_kernel, cudaFuncAttributeMaxDynamicSharedMemorySize,
                         SCAN_SMEM_BYTES);

    dim3 grid(24, Tn);
    xproj_kernel<<<grid, 256>>>(data, icWf, icWb, ciWf, ciWb,
                                icbf, icbb, cibf, cibb,
                                ich0, cih0, out);

    scan_kernel<<<128, 256, SCAN_SMEM_BYTES>>>(icUf, icUb, ciUf, ciUb,
                                               Wm, bm, Wlv, blv, out);
}

// round 12
// speedup vs baseline: 1.9309x; 1.0812x over previous
#include <cuda_runtime.h>
#include <math.h>

#define Tn 1024
#define Bn 128
#define Nn 256
#define Dn 256

// ---------------- static device scratch ----------------
// g_XP[((t*4 + g)*768 + col)*128 + b]
__device__ float g_XP[(size_t)Bn * Tn * 3072];
// g_H / g_RH: [(g*4 + pgroup)*256 + k]*32 + b32   (batch-group-sliced)
__device__ float g_H [16 * 256 * 32];
__device__ float g_RH[16 * 256 * 32];
// phased counters: [(gi*4 + which)*16], which: 0=rh_half0, 1=rh_half1, 2=h_half0, 3=h_half1
__device__ unsigned g_cnt[1024];
__device__ unsigned g_headbar;

// ---------------- f32x2 helpers ----------------
static __device__ __forceinline__ unsigned long long pk2(float lo, float hi) {
    unsigned long long r;
    asm("mov.b64 %0, {%1, %2};" : "=l"(r) : "f"(lo), "f"(hi));
    return r;
}
static __device__ __forceinline__ void up2(unsigned long long v, float& lo, float& hi) {
    asm("mov.b64 {%0, %1}, %2;" : "=f"(lo), "=f"(hi) : "l"(v));
}
static __device__ __forceinline__ void fma2(unsigned long long& d,
                                            unsigned long long a,
                                            unsigned long long b) {
    asm("fma.rn.f32x2 %0, %1, %2, %0;" : "+l"(d) : "l"(a), "l"(b));
}
static __device__ __forceinline__ float sigf(float x) {
    return 1.0f / (1.0f + __expf(-x));
}
static __device__ __forceinline__ float tanhfast(float x) {
    float e = __expf(2.0f * x);
    return 1.0f - 2.0f / (e + 1.0f);
}

// ---------------- cp.async helpers ----------------
static __device__ __forceinline__ void cpa16(void* smem, const void* gmem) {
    unsigned s = (unsigned)__cvta_generic_to_shared(smem);
    asm volatile("cp.async.cg.shared.global [%0], [%1], 16;" :: "r"(s), "l"(gmem));
}
#define CPA_COMMIT() asm volatile("cp.async.commit_group;")
#define CPA_WAIT(n)  asm volatile("cp.async.wait_group %0;" :: "n"(n))

// single-thread poll, then CTA-wide release
static __device__ __forceinline__ void wait_cnt(volatile unsigned* c, unsigned tgt) {
    if (threadIdx.x == 0) {
        while (*c < tgt) { __nanosleep(20); }
    }
    __syncthreads();
}

// ---------------- xproj SGEMM (f32x2, transposed output) + folded init ----------------
__global__ void __launch_bounds__(256) xproj_kernel(
    const float* __restrict__ X,
    const float* __restrict__ W0, const float* __restrict__ W1,
    const float* __restrict__ W2, const float* __restrict__ W3,
    const float* __restrict__ b0, const float* __restrict__ b1,
    const float* __restrict__ b2, const float* __restrict__ b3,
    const float* __restrict__ ich0, const float* __restrict__ cih0,
    float* __restrict__ out)
{
    __shared__ float As[8][128];
    __shared__ float Bs[8][128];

    const int t_  = blockIdx.y;
    const int n0  = blockIdx.x * 128;
    const int g   = n0 / 768;
    const int nc  = n0 - g * 768;
    const float* W    = (g == 0) ? W0 : (g == 1) ? W1 : (g == 2) ? W2 : W3;
    const float* bias = (g == 0) ? b0 : (g == 1) ? b1 : (g == 2) ? b2 : b3;

    const int tid  = threadIdx.x;
    const int warp = tid >> 5, lane = tid & 31;
    const int row0 = (warp & 3) * 32 + (lane >> 3) * 8;
    const int col0 = (warp >> 2) * 64 + (lane & 7) * 8;

    const int am = tid >> 1, ak = (tid & 1) * 4;
    const int bk = tid >> 5, bn = (tid & 31) * 4;

    // ---- folded init (24 blocks with t_==0) ----
    if (t_ == 0) {
        float* ci = out + 32768;
        for (int i = blockIdx.x * 256 + tid; i < Bn * Dn; i += 24 * 256) {
            int b = i >> 8, d = i & 255;
            ci[((size_t)b * Tn) * 512 + d] = 0.0f;
            ci[((size_t)b * Tn + (Tn - 1)) * 512 + 256 + d] = 0.0f;
        }
        for (int i = blockIdx.x * 256 + tid; i < 1024; i += 24 * 256)
            g_cnt[i] = 0u;
        if (blockIdx.x == 0 && tid == 0) g_headbar = 0u;
        for (int i = blockIdx.x * 256 + tid; i < 16 * 8192; i += 24 * 256) {
            int gi = i >> 13;
            int gg = gi >> 2;
            int k  = (i >> 5) & 255;
            const float* h0 = (gg < 2) ? ich0 : cih0;
            g_H[i] = h0[(gg & 1) * Dn + k];
        }
    }

    unsigned long long acc[8][4];
    #pragma unroll
    for (int i = 0; i < 8; i++)
        #pragma unroll
        for (int j = 0; j < 4; j++) acc[i][j] = 0ULL;

    for (int k0 = 0; k0 < 256; k0 += 8) {
        float4 av = __ldg((const float4*)&X[(size_t)am * (Tn * 256) + t_ * 256 + k0 + ak]);
        float4 bv = __ldg((const float4*)&W[(size_t)(k0 + bk) * 768 + nc + bn]);
        __syncthreads();
        As[ak + 0][am] = av.x; As[ak + 1][am] = av.y;
        As[ak + 2][am] = av.z; As[ak + 3][am] = av.w;
        *(float4*)&Bs[bk][bn] = bv;
        __syncthreads();

        #pragma unroll
        for (int kk = 0; kk < 8; ++kk) {
            float4 a0 = *(const float4*)&As[kk][row0];
            float4 a1 = *(const float4*)&As[kk][row0 + 4];
            ulonglong2 b01 = *(const ulonglong2*)&Bs[kk][col0];
            ulonglong2 b23 = *(const ulonglong2*)&Bs[kk][col0 + 4];
            float ar[8] = {a0.x, a0.y, a0.z, a0.w, a1.x, a1.y, a1.z, a1.w};
            #pragma unroll
            for (int i = 0; i < 8; i++) {
                unsigned long long ai = pk2(ar[i], ar[i]);
                fma2(acc[i][0], ai, b01.x);
                fma2(acc[i][1], ai, b01.y);
                fma2(acc[i][2], ai, b23.x);
                fma2(acc[i][3], ai, b23.y);
            }
        }
    }

    float c[8][8];
    #pragma unroll
    for (int i = 0; i < 8; i++) {
        up2(acc[i][0], c[i][0], c[i][1]);
        up2(acc[i][1], c[i][2], c[i][3]);
        up2(acc[i][2], c[i][4], c[i][5]);
        up2(acc[i][3], c[i][6], c[i][7]);
    }
    #pragma unroll
    for (int j = 0; j < 8; j++) {
        float bb = bias[nc + col0 + j];
        size_t base = ((size_t)(t_ * 4 + g) * 768 + nc + col0 + j) * 128 + row0;
        float4 v0 = make_float4(c[0][j] + bb, c[1][j] + bb, c[2][j] + bb, c[3][j] + bb);
        float4 v1 = make_float4(c[4][j] + bb, c[5][j] + bb, c[6][j] + bb, c[7][j] + bb);
        __stcg((float4*)&g_XP[base],     v0);
        __stcg((float4*)&g_XP[base + 4], v1);
    }
}

// ---------------- scan smem layout (floats) ----------------
#define HS_OFF   0                        // 8192  : H/RH batch-slice [256][32]
#define U1_OFF   8192                     // 16384 : zr U slab [256][64]
#define U2_OFF   (U1_OFF + 16384)         // 8192  : hh U slab [256][32]
#define XP_OFF   (U2_OFF + 8192)          // 6144  : XP double buffer [2][96][32]
#define ZS_OFF   (XP_OFF + 6144)          // 1024  : z gate [32][32]
#define HSV_OFF  (ZS_OFF + 1024)          // 1024  : saved old-H [32][32]
#define SCAN_SMEM_FLOATS (HSV_OFF + 1024)
#define SCAN_SMEM_BYTES  (SCAN_SMEM_FLOATS * 4)   // 163840 B

// ---------------- persistent scan: 128 CTAs = 4 GRU x 4 bgroup x 8 colslice ----------------
__global__ void __launch_bounds__(256, 1) scan_kernel(
    const float* __restrict__ U0, const float* __restrict__ U1,
    const float* __restrict__ U2, const float* __restrict__ U3,
    const float* __restrict__ Wm, const float* __restrict__ bm,
    const float* __restrict__ Wlv, const float* __restrict__ blv,
    float* __restrict__ out)
{
    extern __shared__ float sm[];
    float* Hs   = sm + HS_OFF;
    float* U1s  = sm + U1_OFF;
    float* U2s  = sm + U2_OFF;
    float* XPd  = sm + XP_OFF;
    float* Zs   = sm + ZS_OFF;
    float* HsSv = sm + HSV_OFF;

    const int g   = blockIdx.x >> 5;
    const int pg  = (blockIdx.x >> 3) & 3;
    const int cs  = blockIdx.x & 7;
    const int d0  = cs * 32;
    const int gi  = g * 4 + pg;
    const int tid = threadIdx.x;
    const int b   = tid & 31;
    const int jo  = tid >> 5;
    const int half = (cs < 4) ? 0 : 1;
    const float* U = (g == 0) ? U0 : (g == 1) ? U1 : (g == 2) ? U2 : U3;

    volatile unsigned* rh0c = &g_cnt[(gi * 4 + 0) * 16];
    volatile unsigned* rh1c = &g_cnt[(gi * 4 + 1) * 16];
    volatile unsigned* h0c  = &g_cnt[(gi * 4 + 2) * 16];
    volatile unsigned* h1c  = &g_cnt[(gi * 4 + 3) * 16];
    unsigned* my_rh = (unsigned*)&g_cnt[(gi * 4 + half) * 16];
    unsigned* my_h  = (unsigned*)&g_cnt[(gi * 4 + 2 + half) * 16];

    // resident U slabs
    for (int i = tid; i < 256 * 64; i += 256) {
        int k = i >> 6, jj = i & 63;
        int col = (jj < 32) ? (d0 + jj) : (256 + d0 + jj - 32);
        U1s[i] = U[k * 768 + col];
    }
    for (int i = tid; i < 256 * 32; i += 256) {
        int k = i >> 5, jj = i & 31;
        U2s[i] = U[k * 768 + 512 + d0 + jj];
    }

    float* myH  = g_H  + gi * 8192;
    float* myRH = g_RH + gi * 8192;
    float* ci   = out + 32768;

    const int j1 = jo * 8;
    const int j2 = jo * 4;

    // ---- prologue: stage H(0) + XP(0), wait all ----
    #pragma unroll
    for (int ch = 0; ch < 2; ch++) {
        #pragma unroll
        for (int r = 0; r < 4; r++)
            cpa16(Hs + ch * 4096 + (r * 256 + tid) * 4,
                  myH + ch * 4096 + (r * 256 + tid) * 4);
        CPA_COMMIT();
    }
    {
        int t0 = (g & 1) ? (Tn - 1) : 0;
        const float* xpb = g_XP + ((size_t)t0 * 4 + g) * 98304;
        #pragma unroll
        for (int i = 0; i < 3; i++) {
            int idx = i * 256 + tid;
            int cl = idx >> 3, seg = idx & 7;
            int gcol = (cl < 32) ? (d0 + cl) : (cl < 64) ? (256 + d0 + cl - 32)
                                             : (512 + d0 + cl - 64);
            cpa16(XPd + cl * 32 + seg * 4, xpb + gcol * 128 + pg * 32 + seg * 4);
        }
        CPA_COMMIT();
    }
    CPA_WAIT(0);
    __syncthreads();

    for (int s = 0; s < Tn; s++) {
        const float* XPc = XPd + (s & 1) * 3072;

        // ---- prefetch XP(s+1) ----
        {
            int sn = (s < Tn - 1) ? (s + 1) : s;
            int tn_ = (g & 1) ? (Tn - 1 - sn) : sn;
            const float* xpb = g_XP + ((size_t)tn_ * 4 + g) * 98304;
            float* dst = XPd + ((s + 1) & 1) * 3072;
            #pragma unroll
            for (int i = 0; i < 3; i++) {
                int idx = i * 256 + tid;
                int cl = idx >> 3, seg = idx & 7;
                int gcol = (cl < 32) ? (d0 + cl) : (cl < 64) ? (256 + d0 + cl - 32)
                                                 : (512 + d0 + cl - 64);
                cpa16(dst + cl * 32 + seg * 4, xpb + gcol * 128 + pg * 32 + seg * 4);
            }
            CPA_COMMIT();
        }

        // ---- acc init (XPc retired during previous step) ----
        unsigned long long acc[4];
        #pragma unroll
        for (int p = 0; p < 4; p++)
            acc[p] = pk2(XPc[(j1 + 2 * p) * 32 + b], XPc[(j1 + 2 * p + 1) * 32 + b]);

        // ---- phased H staging (s>0; s=0 already in Hs from prologue) ----
        if (s > 0) {
            wait_cnt(h0c, (unsigned)(s * 4));
            #pragma unroll
            for (int r = 0; r < 4; r++)
                cpa16(Hs + (r * 256 + tid) * 4, myH + (r * 256 + tid) * 4);
            CPA_COMMIT();
            wait_cnt(h1c, (unsigned)(s * 4));
            #pragma unroll
            for (int r = 0; r < 4; r++)
                cpa16(Hs + 4096 + (r * 256 + tid) * 4, myH + 4096 + (r * 256 + tid) * 4);
            CPA_COMMIT();
        }

        // ---- phase 1: zr pre-activation ----
        CPA_WAIT(1);
        __syncthreads();
        {
            const float* u1p = U1s + j1;
            const float* hp  = Hs + b;
            #pragma unroll 8
            for (int k = 0; k < 128; k++) {
                ulonglong2 ua = *(const ulonglong2*)(u1p);
                ulonglong2 ub = *(const ulonglong2*)(u1p + 4);
                float h = *hp;
                unsigned long long hd = pk2(h, h);
                fma2(acc[0], ua.x, hd); fma2(acc[1], ua.y, hd);
                fma2(acc[2], ub.x, hd); fma2(acc[3], ub.y, hd);
                u1p += 64; hp += 32;
            }
        }
        CPA_WAIT(0);
        __syncthreads();
        {
            const float* u1p = U1s + 128 * 64 + j1;
            const float* hp  = Hs + 128 * 32 + b;
            #pragma unroll 8
            for (int k = 0; k < 128; k++) {
                ulonglong2 ua = *(const ulonglong2*)(u1p);
                ulonglong2 ub = *(const ulonglong2*)(u1p + 4);
                float h = *hp;
                unsigned long long hd = pk2(h, h);
                fma2(acc[0], ua.x, hd); fma2(acc[1], ua.y, hd);
                fma2(acc[2], ub.x, hd); fma2(acc[3], ub.y, hd);
                u1p += 64; hp += 32;
            }
        }

        // epilogue: z -> Zs, r -> rh -> gmem, save own old-H rows
        {
            float v[8];
            #pragma unroll
            for (int p = 0; p < 4; p++) up2(acc[p], v[2 * p], v[2 * p + 1]);
            if (jo < 4) {
                #pragma unroll
                for (int j = 0; j < 8; j++)
                    Zs[(j1 + j) * 32 + b] = sigf(v[j]);
            } else {
                int jb = j1 - 32;
                #pragma unroll
                for (int j = 0; j < 8; j++) {
                    int d = d0 + jb + j;
                    float rh = sigf(v[j]) * Hs[d * 32 + b];
                    __stcg(myRH + d * 32 + b, rh);
                }
            }
            float4 hv = *(const float4*)(Hs + d0 * 32 + tid * 4);
            *(float4*)(HsSv + tid * 4) = hv;
        }
        __syncthreads();
        if (tid == 0) { __threadfence(); atomicAdd(my_rh, 1u); }

        // ---- phased RH staging ----
        wait_cnt(rh0c, (unsigned)((s + 1) * 4));
        #pragma unroll
        for (int r = 0; r < 4; r++)
            cpa16(Hs + (r * 256 + tid) * 4, myRH + (r * 256 + tid) * 4);
        CPA_COMMIT();
        wait_cnt(rh1c, (unsigned)((s + 1) * 4));
        #pragma unroll
        for (int r = 0; r < 4; r++)
            cpa16(Hs + 4096 + (r * 256 + tid) * 4, myRH + 4096 + (r * 256 + tid) * 4);
        CPA_COMMIT();

        // ---- phase 2: candidate + update ----
        unsigned long long acc2[2];
        #pragma unroll
        for (int p = 0; p < 2; p++)
            acc2[p] = pk2(XPc[(64 + j2 + 2 * p) * 32 + b],
                          XPc[(64 + j2 + 2 * p + 1) * 32 + b]);

        CPA_WAIT(1);
        __syncthreads();
        {
            const float* u2p = U2s + j2;
            const float* hp  = Hs + b;
            #pragma unroll 8
            for (int k = 0; k < 128; k++) {
                ulonglong2 u = *(const ulonglong2*)(u2p);
                float h = *hp;
                unsigned long long hd = pk2(h, h);
                fma2(acc2[0], u.x, hd); fma2(acc2[1], u.y, hd);
                u2p += 32; hp += 32;
            }
        }
        CPA_WAIT(0);
        __syncthreads();
        {
            const float* u2p = U2s + 128 * 32 + j2;
            const float* hp  = Hs + 128 * 32 + b;
            #pragma unroll 8
            for (int k = 0; k < 128; k++) {
                ulonglong2 u = *(const ulonglong2*)(u2p);
                float h = *hp;
                unsigned long long hd = pk2(h, h);
                fma2(acc2[0], u.x, hd); fma2(acc2[1], u.y, hd);
                u2p += 32; hp += 32;
            }
        }

        // epilogue: gate combine, clip, write H, publish, then ci
        float hn[4];
        {
            float w[4];
            up2(acc2[0], w[0], w[1]);
            up2(acc2[1], w[2], w[3]);
            #pragma unroll
            for (int j = 0; j < 4; j++) {
                int jl = j2 + j;
                float z  = Zs[jl * 32 + b];
                float ho = HsSv[jl * 32 + b];
                float cand = tanhfast(w[j]);
                float v = z * ho + (1.0f - z) * cand;
                hn[j] = fminf(5.0f, fmaxf(-5.0f, v));
                __stcg(myH + (d0 + jl) * 32 + b, hn[j]);
            }
        }
        __syncthreads();
        if (tid == 0) { __threadfence(); atomicAdd(my_h, 1u); }

        if (g >= 2 && s < Tn - 1) {
            int Bg = pg * 32 + b;
            size_t row = (g == 2)
                ? ((size_t)Bg * Tn + s + 1) * 512 + d0 + j2
                : ((size_t)Bg * Tn + (Tn - 2 - s)) * 512 + 256 + d0 + j2;
            __stcg((float4*)(ci + row), make_float4(hn[0], hn[1], hn[2], hn[3]));
        }
    }

    // ================= fused heads (ic GRUs only) =================
    if (g < 2) {
        __syncthreads();
        if (tid == 0) {
            __threadfence();
            atomicAdd(&g_headbar, 1u);
            while (*((volatile unsigned*)&g_headbar) < 64u) { __nanosleep(64); }
            __threadfence();
        }
        __syncthreads();

        int rank = g * 32 + pg * 8 + cs;
        int b0 = rank * 2;
        float* hn0 = U1s;
        for (int i = tid; i < 2 * 512; i += 256) {
            int bb = i >> 9, kk = i & 511;
            int bat = b0 + bb;
            int pgr = bat >> 5, b32 = bat & 31;
            float v = (kk < 256) ? g_H[pgr * 8192 + kk * 32 + b32]
                                 : g_H[(4 + pgr) * 8192 + (kk - 256) * 32 + b32];
            hn0[i] = v;
        }
        __syncthreads();
        int m  = tid & 127;
        int bb = tid >> 7;
        const float* hv = hn0 + bb * 512;
        float am = bm[m], alv = blv[m];
        for (int k = 0; k < 512; k++) {
            float h = hv[k];
            am  += h * Wm [k * 128 + m];
            alv += h * Wlv[k * 128 + m];
        }
        out[(b0 + bb) * 128 + m] = am;
        out[16384 + (b0 + bb) * 128 + m] = sqrtf(expf(alv) + 1e-4f);
    }
}

// ---------------- launch ----------------
extern "C" void kernel_launch(void* const* d_in, const int* in_sizes, int n_in,
                              void* d_out, int out_size) {
    const float* data = (const float*)d_in[0];
    const float* icWf = (const float*)d_in[1];
    const float* icUf = (const float*)d_in[2];
    const float* icbf = (const float*)d_in[3];
    const float* icWb = (const float*)d_in[4];
    const float* icUb = (const float*)d_in[5];
    const float* icbb = (const float*)d_in[6];
    const float* ich0 = (const float*)d_in[7];
    const float* ciWf = (const float*)d_in[8];
    const float* ciUf = (const float*)d_in[9];
    const float* cibf = (const float*)d_in[10];
    const float* ciWb = (const float*)d_in[11];
    const float* ciUb = (const float*)d_in[12];
    const float* cibb = (const float*)d_in[13];
    const float* cih0 = (const float*)d_in[14];
    const float* Wm   = (const float*)d_in[15];
    const float* bm   = (const float*)d_in[16];
    const float* Wlv  = (const float*)d_in[17];
    const float* blv  = (const float*)d_in[18];
    float* out = (float*)d_out;

    cudaFuncSetAttribute(scan_kernel, cudaFuncAttributeMaxDynamicSharedMemorySize,
                         SCAN_SMEM_BYTES);

    dim3 grid(24, Tn);
    xproj_kernel<<<grid, 256>>>(data, icWf, icWb, ciWf, ciWb,
                                icbf, icbb, cibf, cibb,
                                ich0, cih0, out);

    scan_kernel<<<128, 256, SCAN_SMEM_BYTES>>>(icUf, icUb, ciUf, ciUb,
                                               Wm, bm, Wlv, blv, out);
}